// round 1
// baseline (speedup 1.0000x reference)
#include <cuda_runtime.h>
#include <math.h>

// ---------------------------------------------------------------------------
// GAT 2-layer forward.  N<=50176 nodes, feature widths: 128 -> 128 (2 heads
// x 64) -> 64 (1 head) -> 16.  Softmax max-shift skipped (logits are O(±6),
// shift-invariant).  Scatter via red.global.add.v4.f32.
// ---------------------------------------------------------------------------

#define NMAX 50176

__device__ float g_h1  [NMAX * 128];
__device__ float g_as1 [NMAX * 2];
__device__ float g_ad1 [NMAX * 2];
__device__ float g_agg1[NMAX * 128];
__device__ float g_den1[NMAX * 2];
__device__ float g_x2  [NMAX * 128];
__device__ float g_h2  [NMAX * 64];
__device__ float g_as2 [NMAX];
__device__ float g_ad2 [NMAX];
__device__ float g_agg2[NMAX * 64];
__device__ float g_den2[NMAX];
__device__ int   g_is64;

__device__ __forceinline__ void red_add_v4(float* p, float a, float b, float c, float d) {
    asm volatile("red.global.add.v4.f32 [%0], {%1,%2,%3,%4};"
                 :: "l"(p), "f"(a), "f"(b), "f"(c), "f"(d) : "memory");
}

// ---------------------------------------------------------------------------
// Detect edge_index element width (int64 vs int32 read as int64 garbage).
// ---------------------------------------------------------------------------
__global__ void detect_kernel(const long long* __restrict__ ei, int E, int n) {
    __shared__ int bad;
    if (threadIdx.x == 0) bad = 0;
    __syncthreads();
    int cnt = E < 1024 ? E : 1024;
    for (int i = threadIdx.x; i < cnt; i += blockDim.x) {
        long long v = ei[i];
        if (v < 0 || v >= (long long)n) atomicAdd(&bad, 1);
    }
    __syncthreads();
    if (threadIdx.x == 0) g_is64 = (bad == 0) ? 1 : 0;
}

// ---------------------------------------------------------------------------
// Zero a float4 array.
// ---------------------------------------------------------------------------
__global__ void zero4_kernel(float4* __restrict__ p, int n4) {
    int i = blockIdx.x * blockDim.x + threadIdx.x;
    if (i < n4) p[i] = make_float4(0.f, 0.f, 0.f, 0.f);
}

// ---------------------------------------------------------------------------
// GEMM + attention dots.  K = 128 always.  FT = total out features (128 or 64).
// Grid: (row blocks of 64, FT/64 column blocks).  Block 256 threads handles
// 4 rows x 64 cols per iteration; W tile (128x64 = 32KB) cached in smem.
// Each column block == one attention head, so a_s/a_d reduce stays in-block.
// ---------------------------------------------------------------------------
template <int FT>
__global__ __launch_bounds__(256) void gemm_att_kernel(
    const float* __restrict__ x, const float* __restrict__ W,
    const float* __restrict__ att_s, const float* __restrict__ att_d,
    float* __restrict__ h, float* __restrict__ as_, float* __restrict__ ad_,
    int n)
{
    constexpr int K = 128;
    constexpr int HEADS = FT / 64;
    constexpr int RPB = 64;            // rows per block
    __shared__ float Wsm[K * 64];
    __shared__ float xs[4 * K];
    __shared__ float attS[64], attD[64];
    __shared__ float redS[8], redD[8];

    const int tid  = threadIdx.x;
    const int cb   = blockIdx.y;       // column block == head index
    const int c    = tid & 63;
    const int rsub = tid >> 6;         // 0..3

    for (int i = tid; i < K * 64; i += 256) {
        int k = i >> 6, cc = i & 63;
        Wsm[i] = W[k * FT + cb * 64 + cc];
    }
    if (tid < 64) {
        attS[tid] = att_s[cb * 64 + tid];
        attD[tid] = att_d[cb * 64 + tid];
    }

    const int row0 = blockIdx.x * RPB;
    for (int rb = 0; rb < RPB; rb += 4) {
        __syncthreads();
        // load 4 rows of x (zero-pad out-of-range rows)
        for (int i = tid; i < 4 * K; i += 256) {
            int rr = row0 + rb + (i >> 7);
            xs[i] = (rr < n) ? x[(long long)rr * K + (i & 127)] : 0.f;
        }
        __syncthreads();

        float acc = 0.f;
        const float* xr = &xs[rsub * K];
#pragma unroll
        for (int k = 0; k < K; k++) acc += xr[k] * Wsm[k * 64 + c];

        int row = row0 + rb + rsub;
        if (row < n) h[(long long)row * FT + cb * 64 + c] = acc;

        float ps = acc * attS[c];
        float pd = acc * attD[c];
#pragma unroll
        for (int o = 16; o; o >>= 1) {
            ps += __shfl_xor_sync(0xffffffffu, ps, o);
            pd += __shfl_xor_sync(0xffffffffu, pd, o);
        }
        int w = tid >> 5;
        if ((tid & 31) == 0) { redS[w] = ps; redD[w] = pd; }
        __syncthreads();
        if (tid < 4) {
            int row2 = row0 + rb + tid;
            if (row2 < n) {
                as_[(long long)row2 * HEADS + cb] = redS[2 * tid] + redS[2 * tid + 1];
                ad_[(long long)row2 * HEADS + cb] = redD[2 * tid] + redD[2 * tid + 1];
            }
        }
    }
}

// ---------------------------------------------------------------------------
// Edge aggregation, layer 1: F=128, heads=2.  One warp per edge; lane L owns
// floats [4L, 4L+4) of the 128-wide row; head = L/16.
// Self-loops: edge ids [E, E+n) are (i,i).
// ---------------------------------------------------------------------------
__global__ __launch_bounds__(256) void edge_kernel_l1(
    const long long* __restrict__ ei,
    const float* __restrict__ h, const float* __restrict__ as_,
    const float* __restrict__ ad_,
    float* __restrict__ agg, float* __restrict__ den, int E, int n)
{
    int gw   = (blockIdx.x * blockDim.x + threadIdx.x) >> 5;
    int lane = threadIdx.x & 31;
    if (gw >= E + n) return;

    long long src, dst;
    if (gw < E) {
        if (g_is64) { src = ei[gw]; dst = ei[E + gw]; }
        else { const int* e32 = (const int*)ei; src = e32[gw]; dst = e32[E + gw]; }
    } else {
        src = dst = gw - E;
    }

    int head = lane >> 4;
    float a = as_[src * 2 + head] + ad_[dst * 2 + head];
    a = a > 0.f ? a : 0.2f * a;          // leaky_relu(0.2)
    float w = __expf(a);                 // no max-shift needed (logits O(+-6))

    float4 hv = reinterpret_cast<const float4*>(h)[src * 32 + lane];
    red_add_v4(agg + dst * 128 + lane * 4, hv.x * w, hv.y * w, hv.z * w, hv.w * w);
    if ((lane & 15) == 0) atomicAdd(den + dst * 2 + head, w);
}

// ---------------------------------------------------------------------------
// Edge aggregation, layer 2: F=64, heads=1.  16 lanes per edge (2 edges/warp).
// ---------------------------------------------------------------------------
__global__ __launch_bounds__(256) void edge_kernel_l2(
    const long long* __restrict__ ei,
    const float* __restrict__ h, const float* __restrict__ as_,
    const float* __restrict__ ad_,
    float* __restrict__ agg, float* __restrict__ den, int E, int n)
{
    int gt = blockIdx.x * blockDim.x + threadIdx.x;
    int e  = gt >> 4;
    int ln = gt & 15;
    if (e >= E + n) return;

    long long src, dst;
    if (e < E) {
        if (g_is64) { src = ei[e]; dst = ei[E + e]; }
        else { const int* e32 = (const int*)ei; src = e32[e]; dst = e32[E + e]; }
    } else {
        src = dst = e - E;
    }

    float a = as_[src] + ad_[dst];
    a = a > 0.f ? a : 0.2f * a;
    float w = __expf(a);

    float4 hv = reinterpret_cast<const float4*>(h)[src * 16 + ln];
    red_add_v4(agg + dst * 64 + ln * 4, hv.x * w, hv.y * w, hv.z * w, hv.w * w);
    if (ln == 0) atomicAdd(den + dst, w);
}

// ---------------------------------------------------------------------------
// Finalize layer 1: out = elu(agg/(den+eps) + b1)  -> x2 [n,128]
// ---------------------------------------------------------------------------
__global__ __launch_bounds__(256) void finalize1_kernel(
    const float* __restrict__ agg, const float* __restrict__ den,
    const float* __restrict__ b, float* __restrict__ o, int n)
{
    int i = blockIdx.x * blockDim.x + threadIdx.x;
    if (i >= n * 128) return;
    int c = i & 127;
    int node = i >> 7;
    int head = c >> 6;
    float v = agg[i] / (den[node * 2 + head] + 1e-16f) + b[c];
    o[i] = v > 0.f ? v : expm1f(v);
}

// ---------------------------------------------------------------------------
// Finalize layer 2 + linear(64->16) + sigmoid.  16 nodes per block.
// ---------------------------------------------------------------------------
__global__ __launch_bounds__(256) void final_kernel(
    const float* __restrict__ agg, const float* __restrict__ den,
    const float* __restrict__ b2, const float* __restrict__ lw,
    const float* __restrict__ lb, float* __restrict__ out, int n)
{
    __shared__ float lwsm[64 * 16];
    __shared__ float lbsm[16];
    __shared__ float o2sm[16 * 64];
    int tid = threadIdx.x;
    for (int i = tid; i < 1024; i += 256) lwsm[i] = lw[i];
    if (tid < 16) lbsm[tid] = lb[tid];

    int nb = blockIdx.x * 16;
    for (int t = tid; t < 16 * 64; t += 256) {
        int node = nb + (t >> 6);
        int c = t & 63;
        float v = 0.f;
        if (node < n) {
            v = agg[node * 64 + c] / (den[node] + 1e-16f) + b2[c];
            v = v > 0.f ? v : expm1f(v);
        }
        o2sm[t] = v;
    }
    __syncthreads();

    int node = nb + (tid >> 4);
    int c = tid & 15;
    if (node < n) {
        float s = lbsm[c];
        const float* o = &o2sm[(tid >> 4) << 6];
#pragma unroll
        for (int k = 0; k < 64; k++) s += o[k] * lwsm[k * 16 + c];
        out[node * 16 + c] = 1.f / (1.f + __expf(-s));
    }
}

// ---------------------------------------------------------------------------
extern "C" void kernel_launch(void* const* d_in, const int* in_sizes, int n_in,
                              void* d_out, int out_size)
{
    const float*     x     = (const float*)d_in[0];
    const long long* ei    = (const long long*)d_in[1];
    const float*     W1    = (const float*)d_in[2];
    const float*     asrc1 = (const float*)d_in[3];
    const float*     adst1 = (const float*)d_in[4];
    const float*     b1    = (const float*)d_in[5];
    const float*     W2    = (const float*)d_in[6];
    const float*     asrc2 = (const float*)d_in[7];
    const float*     adst2 = (const float*)d_in[8];
    const float*     b2    = (const float*)d_in[9];
    const float*     lw    = (const float*)d_in[10];
    const float*     lb    = (const float*)d_in[11];

    int n = in_sizes[0] / 128;
    int E = in_sizes[1] / 2;

    float *h1, *as1, *ad1, *agg1, *den1, *x2, *h2, *as2, *ad2, *agg2, *den2;
    cudaGetSymbolAddress((void**)&h1,   g_h1);
    cudaGetSymbolAddress((void**)&as1,  g_as1);
    cudaGetSymbolAddress((void**)&ad1,  g_ad1);
    cudaGetSymbolAddress((void**)&agg1, g_agg1);
    cudaGetSymbolAddress((void**)&den1, g_den1);
    cudaGetSymbolAddress((void**)&x2,   g_x2);
    cudaGetSymbolAddress((void**)&h2,   g_h2);
    cudaGetSymbolAddress((void**)&as2,  g_as2);
    cudaGetSymbolAddress((void**)&ad2,  g_ad2);
    cudaGetSymbolAddress((void**)&agg2, g_agg2);
    cudaGetSymbolAddress((void**)&den2, g_den2);

    // 0) edge index width detection
    detect_kernel<<<1, 256>>>(ei, E, n);

    // 1) zero accumulators
    {
        int n4 = n * 32;  // agg1: n*128 floats
        zero4_kernel<<<(n4 + 255) / 256, 256>>>((float4*)agg1, n4);
        n4 = (n * 2 + 3) / 4;
        zero4_kernel<<<(n4 + 255) / 256, 256>>>((float4*)den1, n4);
        n4 = n * 16;      // agg2: n*64 floats
        zero4_kernel<<<(n4 + 255) / 256, 256>>>((float4*)agg2, n4);
        n4 = (n + 3) / 4;
        zero4_kernel<<<(n4 + 255) / 256, 256>>>((float4*)den2, n4);
    }

    int rowBlocks = (n + 63) / 64;

    // 2) layer-1 GEMM + attention dots
    gemm_att_kernel<128><<<dim3(rowBlocks, 2), 256>>>(x, W1, asrc1, adst1, h1, as1, ad1, n);

    // 3) layer-1 edge aggregation (warp per edge, incl. self-loops)
    {
        long long threads = (long long)(E + n) * 32;
        int blocks = (int)((threads + 255) / 256);
        edge_kernel_l1<<<blocks, 256>>>(ei, h1, as1, ad1, agg1, den1, E, n);
    }

    // 4) finalize layer 1 (softmax-normalize + bias + elu)
    finalize1_kernel<<<(n * 128 + 255) / 256, 256>>>(agg1, den1, b1, x2, n);

    // 5) layer-2 GEMM + attention dots
    gemm_att_kernel<64><<<dim3(rowBlocks, 1), 256>>>(x2, W2, asrc2, adst2, h2, as2, ad2, n);

    // 6) layer-2 edge aggregation (16 lanes per edge)
    {
        long long threads = (long long)(E + n) * 16;
        int blocks = (int)((threads + 255) / 256);
        edge_kernel_l2<<<blocks, 256>>>(ei, h2, as2, ad2, agg2, den2, E, n);
    }

    // 7) finalize layer 2 + linear + sigmoid
    final_kernel<<<(n + 15) / 16, 256>>>(agg2, den2, b2, lw, lb, (float*)d_out, n);
}

// round 2
// speedup vs baseline: 2.0168x; 2.0168x over previous
#include <cuda_runtime.h>
#include <math.h>

// ---------------------------------------------------------------------------
// GAT 2-layer forward, CSR-based aggregation (no atomic scatters on features).
//   128 -> GAT(2 heads x 64, concat) -> elu -> GAT(1 head x 64, mean) -> elu
//   -> linear(64->16) -> sigmoid
// CSR of the edge list is built once per call and reused by both layers.
// Softmax max-shift skipped (logits O(+-6); softmax is shift-invariant).
// ---------------------------------------------------------------------------

#define NMAX 50176
#define EMAX 1200000
#define SCAN_TILE 1024

__device__ float g_h1  [NMAX * 128];
__device__ float g_as1 [NMAX * 2];
__device__ float g_ad1 [NMAX * 2];
__device__ float g_x2  [NMAX * 128];
__device__ float g_h2  [NMAX * 64];
__device__ float g_as2 [NMAX];
__device__ float g_ad2 [NMAX];
__device__ float g_o2  [NMAX * 64];
__device__ int   g_deg [NMAX];
__device__ int   g_rowptr[NMAX + 1];
__device__ int   g_cursor[NMAX];
__device__ int   g_col [EMAX];
__device__ int   g_bsum[256];
__device__ int   g_boff[256];
__device__ int   g_is64;

// ---------------------------------------------------------------------------
// Detect edge_index element width (int64 vs int32).
// ---------------------------------------------------------------------------
__global__ void detect_kernel(const long long* __restrict__ ei, int E, int n) {
    __shared__ int bad;
    if (threadIdx.x == 0) bad = 0;
    __syncthreads();
    int cnt = E < 1024 ? E : 1024;
    for (int i = threadIdx.x; i < cnt; i += blockDim.x) {
        long long v = ei[i];
        if (v < 0 || v >= (long long)n) atomicAdd(&bad, 1);
    }
    __syncthreads();
    if (threadIdx.x == 0) g_is64 = (bad == 0) ? 1 : 0;
}

__global__ void zero_deg_kernel(int* __restrict__ deg, int n) {
    int i = blockIdx.x * blockDim.x + threadIdx.x;
    if (i < n) deg[i] = 0;
}

// ---------------------------------------------------------------------------
// Histogram of destination degrees.
// ---------------------------------------------------------------------------
__global__ void hist_kernel(const long long* __restrict__ ei, int* __restrict__ deg, int E) {
    int e = blockIdx.x * blockDim.x + threadIdx.x;
    if (e >= E) return;
    int dst;
    if (g_is64) dst = (int)ei[E + e];
    else        dst = ((const int*)ei)[E + e];
    atomicAdd(&deg[dst], 1);
}

// ---------------------------------------------------------------------------
// 3-step exclusive scan of deg -> rowptr (+ cursor copy).
// ---------------------------------------------------------------------------
__global__ __launch_bounds__(256) void scan1_kernel(const int* __restrict__ deg,
                                                    int* __restrict__ bsum, int n) {
    __shared__ int sm[256];
    int base = blockIdx.x * SCAN_TILE;
    int s = 0;
    for (int i = base + threadIdx.x; i < base + SCAN_TILE && i < n; i += 256) s += deg[i];
    sm[threadIdx.x] = s;
    __syncthreads();
    for (int off = 128; off; off >>= 1) {
        if (threadIdx.x < off) sm[threadIdx.x] += sm[threadIdx.x + off];
        __syncthreads();
    }
    if (threadIdx.x == 0) bsum[blockIdx.x] = sm[0];
}

__global__ void scan2_kernel(const int* __restrict__ bsum, int* __restrict__ boff, int nb) {
    if (threadIdx.x == 0) {
        int acc = 0;
        for (int b = 0; b < nb; b++) { boff[b] = acc; acc += bsum[b]; }
    }
}

__global__ __launch_bounds__(256) void scan3_kernel(const int* __restrict__ deg,
                                                    const int* __restrict__ boff,
                                                    int* __restrict__ rowptr,
                                                    int* __restrict__ cursor,
                                                    int n, int E) {
    __shared__ int sm[256];
    int base = blockIdx.x * SCAN_TILE;
    int tid = threadIdx.x;
    int v[4];
    int tsum = 0;
#pragma unroll
    for (int m = 0; m < 4; m++) {
        int i = base + tid * 4 + m;
        v[m] = (i < n) ? deg[i] : 0;
        tsum += v[m];
    }
    sm[tid] = tsum;
    __syncthreads();
    int run = tsum;
    for (int off = 1; off < 256; off <<= 1) {
        int t = (tid >= off) ? sm[tid - off] : 0;
        __syncthreads();
        sm[tid] += t;
        __syncthreads();
    }
    int excl = sm[tid] - run + boff[blockIdx.x];
#pragma unroll
    for (int m = 0; m < 4; m++) {
        int i = base + tid * 4 + m;
        if (i < n) { rowptr[i] = excl; cursor[i] = excl; }
        excl += v[m];
    }
    if (blockIdx.x == 0 && tid == 0) rowptr[n] = E;
}

// ---------------------------------------------------------------------------
// Scatter edge sources into CSR order.
// ---------------------------------------------------------------------------
__global__ void scatter_kernel(const long long* __restrict__ ei,
                               int* __restrict__ cursor, int* __restrict__ col, int E) {
    int e = blockIdx.x * blockDim.x + threadIdx.x;
    if (e >= E) return;
    int src, dst;
    if (g_is64) { src = (int)ei[e]; dst = (int)ei[E + e]; }
    else { src = ((const int*)ei)[e]; dst = ((const int*)ei)[E + e]; }
    int pos = atomicAdd(&cursor[dst], 1);
    col[pos] = src;
}

// ---------------------------------------------------------------------------
// Register-tiled GEMM: h = x @ W.  K = 128.  Thread computes 4 rows x 8 cols.
// FT=128: block tile 64x128.  FT=64: block tile 128x64.  Smem = 48KB.
// ---------------------------------------------------------------------------
template <int FT>
__global__ __launch_bounds__(256) void gemm_kernel(const float* __restrict__ x,
                                                   const float* __restrict__ W,
                                                   float* __restrict__ h, int n) {
    constexpr int ROWS = (FT == 128) ? 64 : 128;
    constexpr int CQ8  = FT / 8;
    __shared__ float xs[ROWS * 64];
    __shared__ float Wsm[64 * FT];

    const int tid = threadIdx.x;
    const int cq  = tid % CQ8;
    const int rq  = tid / CQ8;
    const int row0 = blockIdx.x * ROWS;

    float acc[4][8];
#pragma unroll
    for (int j = 0; j < 4; j++)
#pragma unroll
        for (int c = 0; c < 8; c++) acc[j][c] = 0.f;

    for (int kc = 0; kc < 128; kc += 64) {
        for (int q = tid; q < ROWS * 16; q += 256) {
            int r = q >> 4, kq = q & 15;
            float4 v = make_float4(0.f, 0.f, 0.f, 0.f);
            if (row0 + r < n)
                v = *(const float4*)&x[(long long)(row0 + r) * 128 + kc + kq * 4];
            *(float4*)&xs[r * 64 + kq * 4] = v;
        }
        for (int q = tid; q < 64 * (FT / 4); q += 256) {
            int kk = q / (FT / 4), c4 = q % (FT / 4);
            *(float4*)&Wsm[kk * FT + c4 * 4] = *(const float4*)&W[(kc + kk) * FT + c4 * 4];
        }
        __syncthreads();
#pragma unroll 16
        for (int k = 0; k < 64; k++) {
            float4 wa = *(float4*)&Wsm[k * FT + cq * 8];
            float4 wb = *(float4*)&Wsm[k * FT + cq * 8 + 4];
#pragma unroll
            for (int j = 0; j < 4; j++) {
                float xv = xs[(rq * 4 + j) * 64 + k];
                acc[j][0] += xv * wa.x;
                acc[j][1] += xv * wa.y;
                acc[j][2] += xv * wa.z;
                acc[j][3] += xv * wa.w;
                acc[j][4] += xv * wb.x;
                acc[j][5] += xv * wb.y;
                acc[j][6] += xv * wb.z;
                acc[j][7] += xv * wb.w;
            }
        }
        __syncthreads();
    }
#pragma unroll
    for (int j = 0; j < 4; j++) {
        int r = row0 + rq * 4 + j;
        if (r < n) {
            float4 a = make_float4(acc[j][0], acc[j][1], acc[j][2], acc[j][3]);
            float4 b = make_float4(acc[j][4], acc[j][5], acc[j][6], acc[j][7]);
            *(float4*)&h[(long long)r * FT + cq * 8]     = a;
            *(float4*)&h[(long long)r * FT + cq * 8 + 4] = b;
        }
    }
}

// ---------------------------------------------------------------------------
// Attention dot products: a_s[i,h] = h[i,h,:].att_s[h], a_d likewise.
// ---------------------------------------------------------------------------
template <int HEADS>
__global__ __launch_bounds__(256) void attdots_kernel(const float* __restrict__ h,
                                                      const float* __restrict__ attS,
                                                      const float* __restrict__ attD,
                                                      float* __restrict__ as_,
                                                      float* __restrict__ ad_, int n) {
    int gw   = (blockIdx.x * blockDim.x + threadIdx.x) >> 5;
    int lane = threadIdx.x & 31;
    const float4* h4 = (const float4*)h;
    const float4* s4 = (const float4*)attS;
    const float4* d4 = (const float4*)attD;
    if (HEADS == 2) {
        int node = gw;
        if (node >= n) return;
        int head = lane >> 4, ln = lane & 15;
        float4 hv = h4[(long long)node * 32 + lane];
        float4 aS = s4[head * 16 + ln];
        float4 aD = d4[head * 16 + ln];
        float ps = hv.x * aS.x + hv.y * aS.y + hv.z * aS.z + hv.w * aS.w;
        float pd = hv.x * aD.x + hv.y * aD.y + hv.z * aD.z + hv.w * aD.w;
#pragma unroll
        for (int o = 8; o; o >>= 1) {
            ps += __shfl_xor_sync(0xffffffffu, ps, o);
            pd += __shfl_xor_sync(0xffffffffu, pd, o);
        }
        if (ln == 0) { as_[node * 2 + head] = ps; ad_[node * 2 + head] = pd; }
    } else {
        int node = gw * 2 + (lane >> 4);
        int ln = lane & 15;
        float ps = 0.f, pd = 0.f;
        if (node < n) {
            float4 hv = h4[(long long)node * 16 + ln];
            float4 aS = s4[ln];
            float4 aD = d4[ln];
            ps = hv.x * aS.x + hv.y * aS.y + hv.z * aS.z + hv.w * aS.w;
            pd = hv.x * aD.x + hv.y * aD.y + hv.z * aD.z + hv.w * aD.w;
        }
#pragma unroll
        for (int o = 8; o; o >>= 1) {
            ps += __shfl_xor_sync(0xffffffffu, ps, o);
            pd += __shfl_xor_sync(0xffffffffu, pd, o);
        }
        if (ln == 0 && node < n) { as_[node] = ps; ad_[node] = pd; }
    }
}

__device__ __forceinline__ float leaky_exp(float a) {
    a = a > 0.f ? a : 0.2f * a;
    return __expf(a);
}

// ---------------------------------------------------------------------------
// Layer-1 aggregation (CSR): warp per node, F=128, 2 heads.
// Fuses softmax normalize + bias + ELU; writes x2.
// ---------------------------------------------------------------------------
__global__ __launch_bounds__(256) void agg1_kernel(const int* __restrict__ rowptr,
                                                   const int* __restrict__ col,
                                                   const float* __restrict__ h,
                                                   const float* __restrict__ as_,
                                                   const float* __restrict__ ad_,
                                                   const float* __restrict__ b1,
                                                   float* __restrict__ o, int n) {
    int i    = (blockIdx.x * blockDim.x + threadIdx.x) >> 5;
    int lane = threadIdx.x & 31;
    if (i >= n) return;
    int head = lane >> 4;
    const float4* h4 = (const float4*)h;

    float adv = ad_[i * 2 + head];
    // self loop
    float w = leaky_exp(as_[i * 2 + head] + adv);
    float4 hv = h4[(long long)i * 32 + lane];
    float4 acc = make_float4(hv.x * w, hv.y * w, hv.z * w, hv.w * w);
    float den = w;

    int s0 = rowptr[i], s1 = rowptr[i + 1];
    for (int j = s0; j < s1; j++) {
        int s = col[j];
        w = leaky_exp(as_[s * 2 + head] + adv);
        hv = h4[(long long)s * 32 + lane];
        acc.x += hv.x * w; acc.y += hv.y * w; acc.z += hv.z * w; acc.w += hv.w * w;
        den += w;
    }
    float inv = 1.f / (den + 1e-16f);
    float4 bv = ((const float4*)b1)[lane];
    float4 v;
    v.x = acc.x * inv + bv.x;
    v.y = acc.y * inv + bv.y;
    v.z = acc.z * inv + bv.z;
    v.w = acc.w * inv + bv.w;
    v.x = v.x > 0.f ? v.x : expm1f(v.x);
    v.y = v.y > 0.f ? v.y : expm1f(v.y);
    v.z = v.z > 0.f ? v.z : expm1f(v.z);
    v.w = v.w > 0.f ? v.w : expm1f(v.w);
    ((float4*)o)[(long long)i * 32 + lane] = v;
}

// ---------------------------------------------------------------------------
// Layer-2 aggregation (CSR): warp per node, F=64, 1 head, 2 edges per iter.
// Fuses normalize + bias + ELU; writes o2.
// ---------------------------------------------------------------------------
__global__ __launch_bounds__(256) void agg2_kernel(const int* __restrict__ rowptr,
                                                   const int* __restrict__ col,
                                                   const float* __restrict__ h,
                                                   const float* __restrict__ as_,
                                                   const float* __restrict__ ad_,
                                                   const float* __restrict__ b2,
                                                   float* __restrict__ o, int n) {
    int i    = (blockIdx.x * blockDim.x + threadIdx.x) >> 5;
    int lane = threadIdx.x & 31;
    if (i >= n) return;
    int sub = lane >> 4, ln = lane & 15;
    const float4* h4 = (const float4*)h;

    float adv = ad_[i];
    float4 acc = make_float4(0.f, 0.f, 0.f, 0.f);
    float den = 0.f;
    if (sub == 0) {  // self loop
        float w = leaky_exp(as_[i] + adv);
        float4 hv = h4[(long long)i * 16 + ln];
        acc = make_float4(hv.x * w, hv.y * w, hv.z * w, hv.w * w);
        den = w;
    }
    int s0 = rowptr[i], s1 = rowptr[i + 1];
    for (int j = s0 + sub; j < s1; j += 2) {
        int s = col[j];
        float w = leaky_exp(as_[s] + adv);
        float4 hv = h4[(long long)s * 16 + ln];
        acc.x += hv.x * w; acc.y += hv.y * w; acc.z += hv.z * w; acc.w += hv.w * w;
        den += w;
    }
    acc.x += __shfl_xor_sync(0xffffffffu, acc.x, 16);
    acc.y += __shfl_xor_sync(0xffffffffu, acc.y, 16);
    acc.z += __shfl_xor_sync(0xffffffffu, acc.z, 16);
    acc.w += __shfl_xor_sync(0xffffffffu, acc.w, 16);
    den   += __shfl_xor_sync(0xffffffffu, den, 16);
    if (sub == 0) {
        float inv = 1.f / (den + 1e-16f);
        float4 bv = ((const float4*)b2)[ln];
        float4 v;
        v.x = acc.x * inv + bv.x;
        v.y = acc.y * inv + bv.y;
        v.z = acc.z * inv + bv.z;
        v.w = acc.w * inv + bv.w;
        v.x = v.x > 0.f ? v.x : expm1f(v.x);
        v.y = v.y > 0.f ? v.y : expm1f(v.y);
        v.z = v.z > 0.f ? v.z : expm1f(v.z);
        v.w = v.w > 0.f ? v.w : expm1f(v.w);
        ((float4*)o)[(long long)i * 16 + ln] = v;
    }
}

// ---------------------------------------------------------------------------
// Final linear(64->16) + sigmoid.  16 nodes per block.
// ---------------------------------------------------------------------------
__global__ __launch_bounds__(256) void final_kernel(const float* __restrict__ o2,
                                                    const float* __restrict__ lw,
                                                    const float* __restrict__ lb,
                                                    float* __restrict__ out, int n) {
    __shared__ float lwsm[64 * 16];
    __shared__ float lbsm[16];
    __shared__ float o2sm[16 * 64];
    int tid = threadIdx.x;
    for (int i = tid; i < 1024; i += 256) lwsm[i] = lw[i];
    if (tid < 16) lbsm[tid] = lb[tid];

    int nb = blockIdx.x * 16;
    for (int t = tid; t < 16 * 64; t += 256) {
        int node = nb + (t >> 6);
        o2sm[t] = (node < n) ? o2[(long long)node * 64 + (t & 63)] : 0.f;
    }
    __syncthreads();

    int node = nb + (tid >> 4);
    int c = tid & 15;
    if (node < n) {
        float s = lbsm[c];
        const float* ov = &o2sm[(tid >> 4) << 6];
#pragma unroll
        for (int k = 0; k < 64; k++) s += ov[k] * lwsm[k * 16 + c];
        out[(long long)node * 16 + c] = 1.f / (1.f + __expf(-s));
    }
}

// ---------------------------------------------------------------------------
extern "C" void kernel_launch(void* const* d_in, const int* in_sizes, int n_in,
                              void* d_out, int out_size)
{
    const float*     x     = (const float*)d_in[0];
    const long long* ei    = (const long long*)d_in[1];
    const float*     W1    = (const float*)d_in[2];
    const float*     asrc1 = (const float*)d_in[3];
    const float*     adst1 = (const float*)d_in[4];
    const float*     b1    = (const float*)d_in[5];
    const float*     W2    = (const float*)d_in[6];
    const float*     asrc2 = (const float*)d_in[7];
    const float*     adst2 = (const float*)d_in[8];
    const float*     b2    = (const float*)d_in[9];
    const float*     lw    = (const float*)d_in[10];
    const float*     lb    = (const float*)d_in[11];

    int n = in_sizes[0] / 128;
    int E = in_sizes[1] / 2;

    float *h1, *as1, *ad1, *x2, *h2, *as2, *ad2, *o2;
    int *deg, *rowptr, *cursor, *col, *bsum, *boff;
    cudaGetSymbolAddress((void**)&h1,     g_h1);
    cudaGetSymbolAddress((void**)&as1,    g_as1);
    cudaGetSymbolAddress((void**)&ad1,    g_ad1);
    cudaGetSymbolAddress((void**)&x2,     g_x2);
    cudaGetSymbolAddress((void**)&h2,     g_h2);
    cudaGetSymbolAddress((void**)&as2,    g_as2);
    cudaGetSymbolAddress((void**)&ad2,    g_ad2);
    cudaGetSymbolAddress((void**)&o2,     g_o2);
    cudaGetSymbolAddress((void**)&deg,    g_deg);
    cudaGetSymbolAddress((void**)&rowptr, g_rowptr);
    cudaGetSymbolAddress((void**)&cursor, g_cursor);
    cudaGetSymbolAddress((void**)&col,    g_col);
    cudaGetSymbolAddress((void**)&bsum,   g_bsum);
    cudaGetSymbolAddress((void**)&boff,   g_boff);

    int nb = (n + SCAN_TILE - 1) / SCAN_TILE;

    // (0..4) CSR prologue
    detect_kernel<<<1, 256>>>(ei, E, n);
    zero_deg_kernel<<<(n + 255) / 256, 256>>>(deg, n);
    hist_kernel<<<(E + 255) / 256, 256>>>(ei, deg, E);
    scan1_kernel<<<nb, 256>>>(deg, bsum, n);
    scan2_kernel<<<1, 32>>>(bsum, boff, nb);
    // (5) layer-1 GEMM  (placed at launch index 5 so ncu -s5 profiles it)
    gemm_kernel<128><<<(n + 63) / 64, 256>>>(x, W1, h1, n);
    // (6..7) CSR finish
    scan3_kernel<<<nb, 256>>>(deg, boff, rowptr, cursor, n, E);
    scatter_kernel<<<(E + 255) / 256, 256>>>(ei, cursor, col, E);
    // (8) attention dots layer 1
    attdots_kernel<2><<<(n * 32 + 255) / 256, 256>>>(h1, asrc1, adst1, as1, ad1, n);
    // (9) layer-1 aggregation -> x2 (fused normalize/bias/elu)
    agg1_kernel<<<(n * 32 + 255) / 256, 256>>>(rowptr, col, h1, as1, ad1, b1, x2, n);
    // (10) layer-2 GEMM
    gemm_kernel<64><<<(n + 127) / 128, 256>>>(x2, W2, h2, n);
    // (11) attention dots layer 2
    attdots_kernel<1><<<(n * 16 + 255) / 256, 256>>>(h2, asrc2, adst2, as2, ad2, n);
    // (12) layer-2 aggregation -> o2
    agg2_kernel<<<(n * 32 + 255) / 256, 256>>>(rowptr, col, h2, as2, ad2, b2, o2, n);
    // (13) linear + sigmoid
    final_kernel<<<(n + 15) / 16, 256>>>(o2, lw, lb, (float*)d_out, n);
}